// round 10
// baseline (speedup 1.0000x reference)
#include <cuda_runtime.h>
#include <stdint.h>

// Problem constants (match reference setup)
#define NN 100000          // N_NODES
#define DIM 256            // DIM_ATTEN
#define DIM4 (DIM / 4)     // float4 per node row (64)
#define HASH_BITS 22
#define HASH_SIZE (1u << HASH_BITS)   // 4,194,304 slots x u32 = 16 MB
#define HASH_MASK (HASH_SIZE - 1u)

#define TOTAL4 ((unsigned)NN * DIM4)  // 6,400,000 float4 in node_feature
#define FUSE_BLK 256
#define FUSE_PER_BLK (FUSE_BLK * 4)   // 1024 float4 per block
#define FUSE_FEAT_BLOCKS (TOTAL4 / FUSE_PER_BLK)  // 6250 exactly

// Scratch (device globals — no dynamic allocation allowed)
__device__ unsigned int g_hash[HASH_SIZE];   // 0 = empty, else 32-bit fingerprint
__device__ int g_in_deg[NN];
__device__ int g_out_deg[NN];

// ---------------------------------------------------------------------------
// Kernel 0: clear degree counters (0.8 MB).
// ---------------------------------------------------------------------------
__global__ void deg_clear_kernel() {
    const unsigned tid = blockIdx.x * blockDim.x + threadIdx.x;
    const unsigned stride = gridDim.x * blockDim.x;
    for (unsigned i = tid; i < NN; i += stride) {
        g_in_deg[i] = 0;
        g_out_deg[i] = 0;
    }
}

// ---------------------------------------------------------------------------
// Kernel 1a/1b: clear hash table in two 8 MB halves (split so edge_kernel is
// the 4th launch — the one ncu captures). Also prefetches hash into L2.
// ---------------------------------------------------------------------------
__global__ void hash_clear_half_kernel(unsigned base4) {
    const unsigned tid = blockIdx.x * blockDim.x + threadIdx.x;
    const unsigned stride = gridDim.x * blockDim.x;
    uint4* h4 = reinterpret_cast<uint4*>(g_hash);
    const unsigned n4 = HASH_SIZE / 8;           // half, in uint4 units
    const uint4 z = make_uint4(0u, 0u, 0u, 0u);
    for (unsigned i = tid; i < n4; i += stride) h4[base4 + i] = z;
}

// ---------------------------------------------------------------------------
// Kernel 2: dedup edges via fingerprint hash set (CAS-first probing).
// edge_index is INT32 on device. ONE edge per thread (latency-bound CAS).
// ---------------------------------------------------------------------------
__device__ __forceinline__ unsigned long long mix64(unsigned long long h) {
    h ^= h >> 33;
    h *= 0xff51afd7ed558ccdULL;
    h ^= h >> 33;
    h *= 0xc4ceb9fe1a85ec53ULL;
    h ^= h >> 33;
    return h;
}

__global__ void edge_kernel(const int* __restrict__ edge_index, int n_edges) {
    const int e = blockIdx.x * blockDim.x + threadIdx.x;
    if (e >= n_edges) return;

    int s = edge_index[e];            // row 0: src (coalesced)
    int d = edge_index[e + n_edges];  // row 1: dst (coalesced)
    s = min(max(s, 0), NN - 1);
    d = min(max(d, 0), NN - 1);

    const unsigned long long key =
        (unsigned long long)s * (unsigned long long)NN + (unsigned long long)d;
    const unsigned long long h = mix64(key);
    unsigned slot = (unsigned)h & HASH_MASK;
    unsigned fp = (unsigned)(h >> 32);
    if (fp == 0u) fp = 1u;                       // 0 is the empty sentinel

    while (true) {
        const unsigned prev = atomicCAS(&g_hash[slot], 0u, fp);
        if (prev == 0u) {                        // first occurrence of this pair
            atomicAdd(&g_in_deg[s], 1);          // REDG, fire-and-forget
            atomicAdd(&g_out_deg[d], 1);
            return;
        }
        if (prev == fp) return;                  // duplicate — drop
        slot = (slot + 1) & HASH_MASK;
    }
}

// ---------------------------------------------------------------------------
// Kernel 3: node_feature = x + in_tbl[in_deg] + out_tbl[out_deg]
// COALESCED ILP-4. Degree loads hoisted to the front so the deg->table
// dependency is covered by the 4 in-flight x loads. Output uses __stcs
// (write-streaming: don't allocate the 102 MB store stream in L2).
// Blocks >= FUSE_FEAT_BLOCKS zero the attn_bias tail of d_out.
// ---------------------------------------------------------------------------
__global__ void fuse_kernel(const float4* __restrict__ x,
                            const float4* __restrict__ in_tbl,
                            const float4* __restrict__ out_tbl,
                            float4* __restrict__ out,
                            long long out_elems) {
    const unsigned blk = blockIdx.x;
    if (blk < FUSE_FEAT_BLOCKS) {
        const unsigned base = blk * FUSE_PER_BLK + threadIdx.x;

        unsigned idx[4], node[4], col[4];
#pragma unroll
        for (int k = 0; k < 4; k++) {
            idx[k] = base + k * FUSE_BLK;
            node[k] = idx[k] >> 6;
            col[k]  = idx[k] & 63u;
        }

        // 1) degree loads first (warp-broadcast; start the dependent chain)
        int di[4], dd[4];
#pragma unroll
        for (int k = 0; k < 4; k++) {
            di[k] = g_in_deg[node[k]];
            dd[k] = g_out_deg[node[k]];
        }

        // 2) x loads: 4 independent DRAM streams covering the deg latency
        float4 xv[4];
#pragma unroll
        for (int k = 0; k < 4; k++) xv[k] = x[idx[k]];

        // 3) table gathers (row-contiguous, L2-hot)
        float4 a[4], b[4];
#pragma unroll
        for (int k = 0; k < 4; k++) {
            const int ci = min(max(di[k], 0), 511);
            const int cd = min(max(dd[k], 0), 511);
            a[k] = __ldg(&in_tbl[(unsigned)ci * DIM4 + col[k]]);
            b[k] = __ldg(&out_tbl[(unsigned)cd * DIM4 + col[k]]);
        }

        // 4) add + streaming store
#pragma unroll
        for (int k = 0; k < 4; k++) {
            float4 r;
            r.x = xv[k].x + a[k].x + b[k].x;
            r.y = xv[k].y + a[k].y + b[k].y;
            r.z = xv[k].z + a[k].z + b[k].z;
            r.w = xv[k].w + a[k].w + b[k].w;
            __stcs(&out[idx[k]], r);
        }
    } else {
        // tail zeroing: scalar floats beyond the node_feature region
        const long long tail_tid =
            (long long)(blk - FUSE_FEAT_BLOCKS) * FUSE_BLK + threadIdx.x;
        const long long i = (long long)NN * DIM + tail_tid;
        if (i < out_elems) reinterpret_cast<float*>(out)[i] = 0.0f;
    }
}

// ---------------------------------------------------------------------------
// Launch
// Inputs (metadata order):
//   0: x                 [100000, 256] float32
//   1: edge_feature      [1600000, 128] float32 (zeros — unused)
//   2: edge_index        [2, 1600000] int32
//   3: in_degree_table   [512, 256] float32
//   4: out_degree_table  [512, 256] float32
// Output: node_feature   [100000, 256] float32 (+ possible attn_bias tail)
// ---------------------------------------------------------------------------
extern "C" void kernel_launch(void* const* d_in, const int* in_sizes, int n_in,
                              void* d_out, int out_size) {
    const float4* x        = (const float4*)d_in[0];
    const int* ei          = (const int*)d_in[2];
    const float4* in_tbl   = (const float4*)d_in[3];
    const float4* out_tbl  = (const float4*)d_in[4];
    float4* out            = (float4*)d_out;

    const int n_edges = in_sizes[2] / 2;

    // 1) clear degree counters
    deg_clear_kernel<<<196, 512>>>();

    // 2+3) clear hash in two halves (positions edge_kernel in ncu's slot)
    hash_clear_half_kernel<<<2048, 256>>>(0u);
    hash_clear_half_kernel<<<2048, 256>>>(HASH_SIZE / 8);

    // 4) dedup + degree count (1 edge per thread — latency-bound)
    edge_kernel<<<(n_edges + 255) / 256, 256>>>(ei, n_edges);

    // 5) fused gather-add + tail zero (HBM-bound streaming kernel)
    const long long nf_elems = (long long)NN * DIM;   // 25,600,000
    long long extra = (long long)out_size - nf_elems;
    if (extra < 0) extra = 0;
    const unsigned tail_blocks = (unsigned)((extra + FUSE_BLK - 1) / FUSE_BLK);
    fuse_kernel<<<FUSE_FEAT_BLOCKS + tail_blocks, FUSE_BLK>>>(
        x, in_tbl, out_tbl, out, (long long)out_size);
}

// round 11
// speedup vs baseline: 1.2349x; 1.2349x over previous
#include <cuda_runtime.h>
#include <stdint.h>

// Problem constants (match reference setup)
#define NN 100000          // N_NODES
#define DIM 256            // DIM_ATTEN
#define DIM4 (DIM / 4)     // float4 per node row (64)
#define HASH_BITS 22
#define HASH_SIZE (1u << HASH_BITS)   // 4,194,304 slots x u32 = 16 MB
#define HASH_MASK (HASH_SIZE - 1u)

#define TOTAL4 ((unsigned)NN * DIM4)  // 6,400,000 float4 in node_feature
#define FUSE_BLK 256
#define FUSE_PER_BLK (FUSE_BLK * 4)   // 1024 float4 per block
#define FUSE_FEAT_BLOCKS (TOTAL4 / FUSE_PER_BLK)  // 6250 exactly
#define NODES_PER_FUSE_BLK 16         // 1024 float4 / 64 per node

// Hash-clear blocks appended to the fuse grid (run last -> L2-recent)
#define HCLR_BLOCKS 1024              // 1024 blk * 256 thr * 64 B = 16.78 MB

// Scratch (device globals — zero-initialized at module load; the pipeline
// maintains the all-zero invariant at entry to edge_kernel on every call)
__device__ unsigned int g_hash[HASH_SIZE];   // 0 = empty, else 32-bit fingerprint
__device__ int g_in_deg[NN];
__device__ int g_out_deg[NN];

// ---------------------------------------------------------------------------
// Kernel 1: dedup edges via fingerprint hash set (CAS-first probing).
// edge_index is INT32 on device. ONE edge per thread (latency-bound CAS).
// Precondition: g_hash and degree arrays are all zero (BSS init on first use,
// re-established by fuse_kernel at the end of every call).
// ---------------------------------------------------------------------------
__device__ __forceinline__ unsigned long long mix64(unsigned long long h) {
    h ^= h >> 33;
    h *= 0xff51afd7ed558ccdULL;
    h ^= h >> 33;
    h *= 0xc4ceb9fe1a85ec53ULL;
    h ^= h >> 33;
    return h;
}

__global__ void edge_kernel(const int* __restrict__ edge_index, int n_edges) {
    const int e = blockIdx.x * blockDim.x + threadIdx.x;
    if (e >= n_edges) return;

    int s = edge_index[e];            // row 0: src (coalesced)
    int d = edge_index[e + n_edges];  // row 1: dst (coalesced)
    s = min(max(s, 0), NN - 1);
    d = min(max(d, 0), NN - 1);

    const unsigned long long key =
        (unsigned long long)s * (unsigned long long)NN + (unsigned long long)d;
    const unsigned long long h = mix64(key);
    unsigned slot = (unsigned)h & HASH_MASK;
    unsigned fp = (unsigned)(h >> 32);
    if (fp == 0u) fp = 1u;                       // 0 is the empty sentinel

    while (true) {
        const unsigned prev = atomicCAS(&g_hash[slot], 0u, fp);
        if (prev == 0u) {                        // first occurrence of this pair
            atomicAdd(&g_in_deg[s], 1);          // REDG, fire-and-forget
            atomicAdd(&g_out_deg[d], 1);
            return;
        }
        if (prev == fp) return;                  // duplicate — drop
        slot = (slot + 1) & HASH_MASK;
    }
}

// ---------------------------------------------------------------------------
// Kernel 2: node_feature = x + in_tbl[in_deg] + out_tbl[out_deg]
// COALESCED ILP-4 (R9 body, measured 36.2us / DRAM 55.8%).
// Additionally:
//   - each fuse block exclusively owns nodes [blk*16, blk*16+16); after its
//     threads have consumed the degree values (clamp computed before the
//     barrier forces load completion), it zeroes its own degree counters.
//   - the LAST HCLR_BLOCKS blocks re-zero the 16 MB hash table, restoring the
//     all-zero invariant for the next call with the lines L2-resident.
//   - tail blocks zero any attn_bias tail of d_out.
// ---------------------------------------------------------------------------
__global__ void fuse_kernel(const float4* __restrict__ x,
                            const float4* __restrict__ in_tbl,
                            const float4* __restrict__ out_tbl,
                            float4* __restrict__ out,
                            long long out_elems,
                            unsigned tail_blocks) {
    const unsigned blk = blockIdx.x;
    if (blk < FUSE_FEAT_BLOCKS) {
        const unsigned base = blk * FUSE_PER_BLK + threadIdx.x;

        unsigned idx[4], node[4], col[4];
        float4 xv[4], a[4], b[4];
        int ci[4], cd[4];
#pragma unroll
        for (int k = 0; k < 4; k++) {
            idx[k] = base + k * FUSE_BLK;
            node[k] = idx[k] >> 6;
            col[k]  = idx[k] & 63u;
        }
        // x loads first: 4 independent DRAM streams
#pragma unroll
        for (int k = 0; k < 4; k++) xv[k] = x[idx[k]];

        // degree loads; clamp forces the loads to complete before the barrier
#pragma unroll
        for (int k = 0; k < 4; k++) {
            ci[k] = min(max(g_in_deg[node[k]], 0), 511);
            cd[k] = min(max(g_out_deg[node[k]], 0), 511);
        }
        __syncthreads();   // all degree reads in this block are done

        // this block exclusively owns its 16 nodes' counters — clear them
        if (threadIdx.x < NODES_PER_FUSE_BLK) {
            const unsigned n0 = blk * NODES_PER_FUSE_BLK + threadIdx.x;
            g_in_deg[n0] = 0;
            g_out_deg[n0] = 0;
        }

        // table gathers (row-contiguous, L2-hot)
#pragma unroll
        for (int k = 0; k < 4; k++) {
            a[k] = __ldg(&in_tbl[(unsigned)ci[k] * DIM4 + col[k]]);
            b[k] = __ldg(&out_tbl[(unsigned)cd[k] * DIM4 + col[k]]);
        }

#pragma unroll
        for (int k = 0; k < 4; k++) {
            float4 r;
            r.x = xv[k].x + a[k].x + b[k].x;
            r.y = xv[k].y + a[k].y + b[k].y;
            r.z = xv[k].z + a[k].z + b[k].z;
            r.w = xv[k].w + a[k].w + b[k].w;
            out[idx[k]] = r;
        }
    } else if (blk < FUSE_FEAT_BLOCKS + tail_blocks) {
        // tail zeroing: scalar floats beyond the node_feature region
        const long long tail_tid =
            (long long)(blk - FUSE_FEAT_BLOCKS) * FUSE_BLK + threadIdx.x;
        const long long i = (long long)NN * DIM + tail_tid;
        if (i < out_elems) reinterpret_cast<float*>(out)[i] = 0.0f;
    } else {
        // hash clear: highest block indices -> executed last -> L2-recent
        const unsigned cb = blk - FUSE_FEAT_BLOCKS - tail_blocks;  // 0..1023
        uint4* h4 = reinterpret_cast<uint4*>(g_hash);
        const unsigned base4 = cb * (FUSE_BLK * 4) + threadIdx.x;
        const uint4 z = make_uint4(0u, 0u, 0u, 0u);
#pragma unroll
        for (int k = 0; k < 4; k++)
            h4[base4 + k * FUSE_BLK] = z;   // 1024*256*4 uint4 = HASH_SIZE/4
    }
}

// ---------------------------------------------------------------------------
// Launch — two kernels per call:
//   1) edge:   dedup + degree count (scratch guaranteed all-zero at entry)
//   2) fuse:   gather-add + per-block degree re-zero + hash re-zero + tail
// Inputs (metadata order):
//   0: x                 [100000, 256] float32
//   1: edge_feature      [1600000, 128] float32 (zeros — unused)
//   2: edge_index        [2, 1600000] int32
//   3: in_degree_table   [512, 256] float32
//   4: out_degree_table  [512, 256] float32
// Output: node_feature   [100000, 256] float32 (+ possible attn_bias tail)
// ---------------------------------------------------------------------------
extern "C" void kernel_launch(void* const* d_in, const int* in_sizes, int n_in,
                              void* d_out, int out_size) {
    const float4* x        = (const float4*)d_in[0];
    const int* ei          = (const int*)d_in[2];
    const float4* in_tbl   = (const float4*)d_in[3];
    const float4* out_tbl  = (const float4*)d_in[4];
    float4* out            = (float4*)d_out;

    const int n_edges = in_sizes[2] / 2;

    // 1) dedup + degree count (1 edge per thread — latency-bound)
    edge_kernel<<<(n_edges + 255) / 256, 256>>>(ei, n_edges);

    // 2) fused gather-add + state re-zero + tail zero
    const long long nf_elems = (long long)NN * DIM;   // 25,600,000
    long long extra = (long long)out_size - nf_elems;
    if (extra < 0) extra = 0;
    const unsigned tail_blocks = (unsigned)((extra + FUSE_BLK - 1) / FUSE_BLK);
    fuse_kernel<<<FUSE_FEAT_BLOCKS + tail_blocks + HCLR_BLOCKS, FUSE_BLK>>>(
        x, in_tbl, out_tbl, out, (long long)out_size, tail_blocks);
}